// round 3
// baseline (speedup 1.0000x reference)
#include <cuda_runtime.h>
#include <cstdint>

typedef unsigned long long u64;

#define NB      16
#define EMB     208
#define KLV     300
#define NPROP   900
#define MAXP    500
#define DPROP   213
#define NWORDS  15      // ceil(900/64)
#define NMS_THR 0.45f
#define NBIN    2048
#define NMAX    23104   // 4*76*76

__constant__ float2 c_anch[3][4] = {
  {{8.f,24.f},{11.f,34.f},{16.f,48.f},{23.f,68.f}},
  {{32.f,96.f},{45.f,135.f},{64.f,192.f},{90.f,271.f}},
  {{128.f,384.f},{180.f,540.f},{256.f,640.f},{512.f,640.f}}
};
__constant__ int   c_H[3]      = {76, 38, 19};
__constant__ float c_stride[3] = {8.f, 16.f, 32.f};

// ---------------- device scratch (no allocations allowed) ----------------
__device__ float4 g_box[NB*NPROP];
__device__ float  g_score[NB*NPROP];
__device__ int    g_src[NB*NPROP];
__device__ float4 g_sbox[NB*NPROP];
__device__ float  g_sscore[NB*NPROP];
__device__ int    g_ssrc[NB*NPROP];
__device__ int    g_kept[NB*MAXP];
__device__ int    g_nkept[NB];

// ---------------- 1) fused per-(image,level) select + top-300 ----------------
__global__ void select_kernel(const float* __restrict__ p0,
                              const float* __restrict__ p1,
                              const float* __restrict__ p2)
{
  const int b     = blockIdx.x;
  const int level = blockIdx.y;
  const int tid   = threadIdx.x;
  const int BS    = blockDim.x;           // 1024

  const float* pred = (level == 0) ? p0 : (level == 1) ? p1 : p2;
  const int H = c_H[level], W = H;
  const int N = 4*H*W;
  const float stride = c_stride[level];
  const float scale  = stride / 608.0f;

  extern __shared__ float ds[];           // [N] d-values, N <= 23104
  __shared__ unsigned int hist[NBIN];
  __shared__ unsigned int csum[64];
  __shared__ float cs[NBIN];
  __shared__ int   ci[NBIN];
  __shared__ int   s_cnt, s_tbin;

  for (int i = tid; i < NBIN; i += BS) hist[i] = 0u;
  if (tid == 0) s_cnt = 0;
  __syncthreads();

  const float* pb = pred + (size_t)b * N * 6;

  // pass 1: d = c - a (ALU only), histogram of positives
  for (int i = tid; i < N; i += BS) {
    float2 v = *(const float2*)(pb + (size_t)i*6 + 4);
    float d = v.y - v.x;
    ds[i] = d;
    if (d > 0.0f) {
      int bin = (int)(d * 128.0f);
      bin = bin > NBIN-1 ? NBIN-1 : bin;
      atomicAdd(&hist[bin], 1u);
    }
  }
  __syncthreads();

  if (tid < 64) {
    unsigned s = 0;
    #pragma unroll
    for (int k = 0; k < 32; k++) s += hist[tid*32 + k];
    csum[tid] = s;
  }
  __syncthreads();
  if (tid == 0) {
    unsigned acc = 0;
    int t = 0;
    int c = 63;
    for (; c >= 0; c--) {
      if (acc + csum[c] >= (unsigned)KLV) break;
      acc += csum[c];
    }
    if (c >= 0) {
      int bb = c*32 + 31;
      for (; bb > c*32; bb--) {
        if (acc + hist[bb] >= (unsigned)KLV) break;
        acc += hist[bb];
      }
      t = bb;
    }
    s_tbin = t;
  }
  __syncthreads();
  const int t = s_tbin;

  // pass 2: collect candidates in bins >= t (from smem)
  for (int i = tid; i < N; i += BS) {
    float d = ds[i];
    if (d > 0.0f) {
      int bin = (int)(d * 128.0f);
      bin = bin > NBIN-1 ? NBIN-1 : bin;
      if (bin >= t) {
        int p = atomicAdd(&s_cnt, 1);
        if (p < NBIN) { cs[p] = d; ci[p] = i; }
      }
    }
  }
  __syncthreads();
  int m = s_cnt; if (m > NBIN) m = NBIN;

  // exact conf (matches reference softmax bitwise) for candidates only
  for (int p = tid; p < m; p += BS) {
    float conf = 1.0f / (1.0f + expf(-cs[p]));
    cs[p] = (conf > 0.5f) ? conf : -1.0f;
  }
  int P = 512; while (P < m) P <<= 1;
  for (int i = tid; i < P; i += BS)
    if (i >= m) { cs[i] = -1.0f; ci[i] = 0x7fffffff; }
  __syncthreads();

  // bitonic sort (conf desc, idx asc) over P elements
  for (int k = 2; k <= P; k <<= 1) {
    for (int j = k >> 1; j > 0; j >>= 1) {
      for (int x = tid; x < P; x += BS) {
        int ixj = x ^ j;
        if (ixj > x) {
          float ca = cs[x], cb = cs[ixj];
          int   ia = ci[x], ib = ci[ixj];
          bool later = (ca < cb) || (ca == cb && ia > ib);
          if (later == ((x & k) == 0)) {
            cs[x] = cb; cs[ixj] = ca;
            ci[x] = ib; ci[ixj] = ia;
          }
        }
      }
      __syncthreads();
    }
  }

  // decode + write top-300 (zero-pad shortfall / sub-threshold)
  if (tid < KLV) {
    const int o = b*NPROP + level*KLV + tid;
    if (tid < m && cs[tid] > 0.5f) {
      float conf = cs[tid];
      int   idx  = ci[tid];
      int hw = H*W;
      int a  = idx / hw;
      int r2 = idx - a*hw;
      int h  = r2 / W;
      int w  = r2 - h*W;
      const float* pp = pb + (size_t)idx*6;
      float aw = c_anch[level][a].x / stride;
      float ah = c_anch[level][a].y / stride;
      float x  = pp[0]*aw + (float)w;
      float y  = pp[1]*ah + (float)h;
      float bw = expf(pp[2])*aw;
      float bh = expf(pp[3])*ah;
      float x1 = fminf(fmaxf((x - 0.5f*bw)*scale, 0.0f), 1.0f);
      float y1 = fminf(fmaxf((y - 0.5f*bh)*scale, 0.0f), 1.0f);
      float x2 = fminf(fmaxf((x + 0.5f*bw)*scale, 0.0f), 1.0f);
      float y2 = fminf(fmaxf((y + 0.5f*bh)*scale, 0.0f), 1.0f);
      g_box[o]   = make_float4(x1, y1, x2, y2);
      g_score[o] = conf;
      g_src[o]   = (level << 26) | idx;
    } else {
      g_box[o]   = make_float4(0.f, 0.f, 0.f, 0.f);
      g_score[o] = 0.f;
      g_src[o]   = -1;
    }
  }
}

// ------- 2) fused per-image: 3-way merge + supp bitmatrix + greedy walk -------
__global__ void nms_kernel()
{
  const int b = blockIdx.x;
  const int t = threadIdx.x;     // 1024
  extern __shared__ u64 ssup[];  // [900*15] suppression matrix, 108000 B

  __shared__ float  s[NPROP];
  __shared__ float  ms[2*KLV];
  __shared__ int    p6[2*KLV];
  __shared__ float  fs[NPROP];
  __shared__ int    p9[NPROP];
  __shared__ float4 sb[NPROP];
  __shared__ float  sa[NPROP];
  __shared__ int    s_nv;

  if (t < NPROP) s[t] = g_score[b*NPROP + t];
  if (t == 0) s_nv = 0;
  __syncthreads();

  // stage 1: merge [0,300) (A) with [300,600) (B); A wins ties
  if (t < 2*KLV) {
    float v; int pos;
    if (t < KLV) {
      v = s[t];
      int lo = 0, hi = KLV;
      while (lo < hi) { int mid = (lo+hi)>>1; if (s[KLV+mid] > v) lo = mid+1; else hi = mid; }
      pos = t + lo;
    } else {
      int j = t - KLV; v = s[t];
      int lo = 0, hi = KLV;
      while (lo < hi) { int mid = (lo+hi)>>1; if (s[mid] >= v) lo = mid+1; else hi = mid; }
      pos = j + lo;
    }
    ms[pos] = v; p6[pos] = t;
  }
  __syncthreads();

  // stage 2: merge AB (600) with C = [600,900); AB wins ties
  if (t < NPROP) {
    float v; int src, pos;
    if (t < 2*KLV) {
      v = ms[t]; src = p6[t];
      int lo = 0, hi = KLV;
      while (lo < hi) { int mid = (lo+hi)>>1; if (s[2*KLV+mid] > v) lo = mid+1; else hi = mid; }
      pos = t + lo;
    } else {
      int j = t - 2*KLV; v = s[t]; src = t;
      int lo = 0, hi = 2*KLV;
      while (lo < hi) { int mid = (lo+hi)>>1; if (ms[mid] >= v) lo = mid+1; else hi = mid; }
      pos = j + lo;
    }
    fs[pos] = v; p9[pos] = src;
  }
  __syncthreads();

  if (t < NPROP) {
    int src = p9[t];
    float4 f = g_box[b*NPROP + src];
    sb[t] = f;
    sa[t] = (f.z - f.x) * (f.w - f.y);
    g_sbox[b*NPROP + t]   = f;
    g_sscore[b*NPROP + t] = fs[t];
    g_ssrc[b*NPROP + t]   = g_src[b*NPROP + src];
    if (fs[t] > 0.f && (t == NPROP-1 || fs[t+1] <= 0.f)) s_nv = t + 1;
  }
  __syncthreads();

  // suppression bitmatrix in smem: bit(i,j) = IoU>thr & j>i
  for (int x = t; x < NPROP*NWORDS; x += 1024) {
    int i = x / NWORDS;
    int w = x - i*NWORDS;
    float4 bi = sb[i];
    float  ai = sa[i];
    u64 bits = 0;
    int j0   = w * 64;
    int jend = j0 + 64; if (jend > NPROP) jend = NPROP;
    for (int j = (j0 > i+1 ? j0 : i+1); j < jend; j++) {
      float4 bj = sb[j];
      float xx1 = fmaxf(bi.x, bj.x);
      float yy1 = fmaxf(bi.y, bj.y);
      float xx2 = fminf(bi.z, bj.z);
      float yy2 = fminf(bi.w, bj.w);
      float inter = fmaxf(xx2 - xx1, 0.f) * fmaxf(yy2 - yy1, 0.f);
      float iou = inter / (ai + sa[j] - inter + 1e-9f);
      if (iou > NMS_THR) bits |= (1ULL << (j - j0));
    }
    ssup[(size_t)i*NWORDS + w] = bits;
  }
  __syncthreads();

  // greedy walk: single thread, register-resident removed-bitmask.
  // Critical path per kept item: one LDS (own-word supp) + ffs + masking.
  if (t == 0) {
    const int nv  = s_nv;
    const int nvw = nv >> 6, nvb = nv & 63;
    int nk = 0;
    u64 rem[NWORDS];
    #pragma unroll
    for (int w = 0; w < NWORDS; w++) {
      u64 valid = (w < nvw) ? ~0ULL
                : (w == nvw ? (nvb ? ((1ULL << nvb) - 1ULL) : 0ULL) : 0ULL);
      rem[w] = ~valid;
    }
    #pragma unroll
    for (int w = 0; w < NWORDS; w++) {
      u64 cur = ~rem[w];
      while (cur != 0 && nk < MAXP) {
        int bit = __ffsll((long long)cur) - 1;
        int i = (w << 6) + bit;
        g_kept[b*MAXP + nk] = i;
        nk++;
        const u64* row = &ssup[(size_t)i*NWORDS];
        u64 sw = row[w];
        #pragma unroll
        for (int u = 0; u < NWORDS; u++)
          if (u > w) rem[u] |= row[u];
        cur &= ~((2ULL << bit) - 1ULL) & ~sw;
      }
      if (nk >= MAXP) break;
    }
    g_nkept[b] = nk;
  }
}

// ------- 3) output: box+score + gathered, L2-normalized embedding -------
__global__ void write_kernel(float* __restrict__ out,
                             const float* __restrict__ e0,
                             const float* __restrict__ e1,
                             const float* __restrict__ e2)
{
  const int b = blockIdx.y;
  const int r = blockIdx.x;
  const int tid = threadIdx.x;
  float* o = out + ((size_t)b*MAXP + r)*DPROP;

  if (r >= g_nkept[b]) {                 // zero row (output is poisoned)
    if (tid < DPROP) o[tid] = 0.0f;
    return;
  }

  const int i   = g_kept[b*MAXP + r];
  const int src = g_ssrc[b*NPROP + i];
  const int level = src >> 26;
  const int idx   = src & ((1 << 26) - 1);
  const int H  = (level == 0) ? 76 : (level == 1 ? 38 : 19);
  const int hw = H*H;
  const int r2 = idx % hw;
  const int h  = r2 / H;
  const int w  = r2 - h*H;
  const float* eb = (level == 0 ? e0 : (level == 1 ? e1 : e2));
  const float* e  = eb + (((size_t)b*H + h)*H + w)*EMB;

  float v = (tid < EMB) ? e[tid] : 0.f;

  // warp-shuffle reduction of v*v, then cross-warp via smem
  float p = v*v;
  #pragma unroll
  for (int s = 16; s > 0; s >>= 1) p += __shfl_xor_sync(0xffffffffu, p, s);
  __shared__ float red[8];
  if ((tid & 31) == 0) red[tid >> 5] = p;
  __syncthreads();
  float tot = red[0]+red[1]+red[2]+red[3]+red[4]+red[5]+red[6]+red[7];
  float rinv = rsqrtf(fmaxf(tot, 1e-12f));

  if (tid < EMB) o[5 + tid] = v * rinv;
  if (tid == 0) {
    float4 bx = g_sbox[b*NPROP + i];
    o[0] = bx.x; o[1] = bx.y; o[2] = bx.z; o[3] = bx.w;
    o[4] = g_sscore[b*NPROP + i];
  }
}

// ---------------------------------------------------------------------------
extern "C" void kernel_launch(void* const* d_in, const int* in_sizes, int n_in,
                              void* d_out, int out_size)
{
  const float *p0=nullptr,*p1=nullptr,*p2=nullptr,*e0=nullptr,*e1=nullptr,*e2=nullptr;
  for (int i = 0; i < n_in; i++) {
    switch (in_sizes[i]) {
      case 2217984:  p0 = (const float*)d_in[i]; break;  // pred0 [16,4,76,76,6]
      case 554496:   p1 = (const float*)d_in[i]; break;  // pred1 [16,4,38,38,6]
      case 138624:   p2 = (const float*)d_in[i]; break;  // pred2 [16,4,19,19,6]
      case 19222528: e0 = (const float*)d_in[i]; break;  // emb0 [16,76,76,208]
      case 4805632:  e1 = (const float*)d_in[i]; break;  // emb1 [16,38,38,208]
      case 1201408:  e2 = (const float*)d_in[i]; break;  // emb2 [16,19,19,208]
    }
  }

  cudaFuncSetAttribute(select_kernel, cudaFuncAttributeMaxDynamicSharedMemorySize,
                       NMAX*(int)sizeof(float));
  select_kernel<<<dim3(NB,3), 1024, NMAX*sizeof(float)>>>(p0, p1, p2);

  cudaFuncSetAttribute(nms_kernel, cudaFuncAttributeMaxDynamicSharedMemorySize,
                       NPROP*NWORDS*(int)sizeof(u64));
  nms_kernel<<<NB, 1024, NPROP*NWORDS*sizeof(u64)>>>();

  write_kernel<<<dim3(MAXP, NB), 256>>>((float*)d_out, e0, e1, e2);
}

// round 4
// speedup vs baseline: 1.0808x; 1.0808x over previous
#include <cuda_runtime.h>
#include <cstdint>

typedef unsigned long long u64;

#define NB      16
#define EMB     208
#define KLV     300
#define NPROP   900
#define MAXP    500
#define DPROP   213
#define NWORDS  15      // ceil(900/64)
#define NMS_THR 0.45f
#define NBIN    2048
#define NMAX    23104   // 4*76*76

__constant__ float2 c_anch[3][4] = {
  {{8.f,24.f},{11.f,34.f},{16.f,48.f},{23.f,68.f}},
  {{32.f,96.f},{45.f,135.f},{64.f,192.f},{90.f,271.f}},
  {{128.f,384.f},{180.f,540.f},{256.f,640.f},{512.f,640.f}}
};
__constant__ int   c_H[3]      = {76, 38, 19};
__constant__ float c_stride[3] = {8.f, 16.f, 32.f};

// ---------------- device scratch (no allocations allowed) ----------------
__device__ float4 g_box[NB*NPROP];
__device__ float  g_score[NB*NPROP];
__device__ int    g_src[NB*NPROP];
__device__ float4 g_sbox[NB*NPROP];
__device__ float  g_sscore[NB*NPROP];
__device__ int    g_ssrc[NB*NPROP];
__device__ int    g_kept[NB*MAXP];
__device__ int    g_nkept[NB];

// ---------------- 1) fused per-(image,level) select + top-300 ----------------
__global__ void select_kernel(const float* __restrict__ p0,
                              const float* __restrict__ p1,
                              const float* __restrict__ p2)
{
  const int b     = blockIdx.x;
  const int level = blockIdx.y;
  const int tid   = threadIdx.x;
  const int BS    = blockDim.x;           // 1024

  const float* pred = (level == 0) ? p0 : (level == 1) ? p1 : p2;
  const int H = c_H[level], W = H;
  const int N = 4*H*W;
  const float stride = c_stride[level];
  const float scale  = stride / 608.0f;

  extern __shared__ float ds[];           // [N] d-values, N <= 23104
  __shared__ unsigned int hist[NBIN];
  __shared__ unsigned int csum[64];
  __shared__ float cs[NBIN];
  __shared__ int   ci[NBIN];
  __shared__ int   s_cnt, s_tbin;

  for (int i = tid; i < NBIN; i += BS) hist[i] = 0u;
  if (tid == 0) s_cnt = 0;
  __syncthreads();

  const float* pb = pred + (size_t)b * N * 6;

  // pass 1: d = c - a (ALU only), histogram of positives
  for (int i = tid; i < N; i += BS) {
    float2 v = *(const float2*)(pb + (size_t)i*6 + 4);
    float d = v.y - v.x;
    ds[i] = d;
    if (d > 0.0f) {
      int bin = (int)(d * 128.0f);
      bin = bin > NBIN-1 ? NBIN-1 : bin;
      atomicAdd(&hist[bin], 1u);
    }
  }
  __syncthreads();

  if (tid < 64) {
    unsigned s = 0;
    #pragma unroll
    for (int k = 0; k < 32; k++) s += hist[tid*32 + k];
    csum[tid] = s;
  }
  __syncthreads();
  if (tid == 0) {
    unsigned acc = 0;
    int t = 0;
    int c = 63;
    for (; c >= 0; c--) {
      if (acc + csum[c] >= (unsigned)KLV) break;
      acc += csum[c];
    }
    if (c >= 0) {
      int bb = c*32 + 31;
      for (; bb > c*32; bb--) {
        if (acc + hist[bb] >= (unsigned)KLV) break;
        acc += hist[bb];
      }
      t = bb;
    }
    s_tbin = t;
  }
  __syncthreads();
  const int t = s_tbin;

  // pass 2: collect candidates in bins >= t (from smem)
  for (int i = tid; i < N; i += BS) {
    float d = ds[i];
    if (d > 0.0f) {
      int bin = (int)(d * 128.0f);
      bin = bin > NBIN-1 ? NBIN-1 : bin;
      if (bin >= t) {
        int p = atomicAdd(&s_cnt, 1);
        if (p < NBIN) { cs[p] = d; ci[p] = i; }
      }
    }
  }
  __syncthreads();
  int m = s_cnt; if (m > NBIN) m = NBIN;

  // exact conf (matches reference softmax bitwise) for candidates only
  for (int p = tid; p < m; p += BS) {
    float conf = 1.0f / (1.0f + expf(-cs[p]));
    cs[p] = (conf > 0.5f) ? conf : -1.0f;
  }
  int P = 512; while (P < m) P <<= 1;
  for (int i = tid; i < P; i += BS)
    if (i >= m) { cs[i] = -1.0f; ci[i] = 0x7fffffff; }
  __syncthreads();

  // bitonic sort (conf desc, idx asc) over P elements
  for (int k = 2; k <= P; k <<= 1) {
    for (int j = k >> 1; j > 0; j >>= 1) {
      for (int x = tid; x < P; x += BS) {
        int ixj = x ^ j;
        if (ixj > x) {
          float ca = cs[x], cb = cs[ixj];
          int   ia = ci[x], ib = ci[ixj];
          bool later = (ca < cb) || (ca == cb && ia > ib);
          if (later == ((x & k) == 0)) {
            cs[x] = cb; cs[ixj] = ca;
            ci[x] = ib; ci[ixj] = ia;
          }
        }
      }
      __syncthreads();
    }
  }

  // decode + write top-300 (zero-pad shortfall / sub-threshold)
  if (tid < KLV) {
    const int o = b*NPROP + level*KLV + tid;
    if (tid < m && cs[tid] > 0.5f) {
      float conf = cs[tid];
      int   idx  = ci[tid];
      int hw = H*W;
      int a  = idx / hw;
      int r2 = idx - a*hw;
      int h  = r2 / W;
      int w  = r2 - h*W;
      const float* pp = pb + (size_t)idx*6;
      float aw = c_anch[level][a].x / stride;
      float ah = c_anch[level][a].y / stride;
      float x  = pp[0]*aw + (float)w;
      float y  = pp[1]*ah + (float)h;
      float bw = expf(pp[2])*aw;
      float bh = expf(pp[3])*ah;
      float x1 = fminf(fmaxf((x - 0.5f*bw)*scale, 0.0f), 1.0f);
      float y1 = fminf(fmaxf((y - 0.5f*bh)*scale, 0.0f), 1.0f);
      float x2 = fminf(fmaxf((x + 0.5f*bw)*scale, 0.0f), 1.0f);
      float y2 = fminf(fmaxf((y + 0.5f*bh)*scale, 0.0f), 1.0f);
      g_box[o]   = make_float4(x1, y1, x2, y2);
      g_score[o] = conf;
      g_src[o]   = (level << 26) | idx;
    } else {
      g_box[o]   = make_float4(0.f, 0.f, 0.f, 0.f);
      g_score[o] = 0.f;
      g_src[o]   = -1;
    }
  }
}

// ------- 2) fused per-image: 3-way merge + supp bitmatrix + greedy walk -------
__global__ void nms_kernel()
{
  const int b = blockIdx.x;
  const int t = threadIdx.x;     // 1024
  extern __shared__ u64 ssup[];  // [900*15] suppression matrix, 108000 B

  __shared__ float  s[NPROP];
  __shared__ float  ms[2*KLV];
  __shared__ int    p6[2*KLV];
  __shared__ float  fs[NPROP];
  __shared__ int    p9[NPROP];
  __shared__ float4 sb[NPROP];
  __shared__ float  sa[NPROP];
  __shared__ int    s_nv;

  if (t < NPROP) s[t] = g_score[b*NPROP + t];
  if (t == 0) s_nv = 0;
  __syncthreads();

  // stage 1: merge [0,300) (A) with [300,600) (B); A wins ties
  if (t < 2*KLV) {
    float v; int pos;
    if (t < KLV) {
      v = s[t];
      int lo = 0, hi = KLV;
      while (lo < hi) { int mid = (lo+hi)>>1; if (s[KLV+mid] > v) lo = mid+1; else hi = mid; }
      pos = t + lo;
    } else {
      int j = t - KLV; v = s[t];
      int lo = 0, hi = KLV;
      while (lo < hi) { int mid = (lo+hi)>>1; if (s[mid] >= v) lo = mid+1; else hi = mid; }
      pos = j + lo;
    }
    ms[pos] = v; p6[pos] = t;
  }
  __syncthreads();

  // stage 2: merge AB (600) with C = [600,900); AB wins ties
  if (t < NPROP) {
    float v; int src, pos;
    if (t < 2*KLV) {
      v = ms[t]; src = p6[t];
      int lo = 0, hi = KLV;
      while (lo < hi) { int mid = (lo+hi)>>1; if (s[2*KLV+mid] > v) lo = mid+1; else hi = mid; }
      pos = t + lo;
    } else {
      int j = t - 2*KLV; v = s[t]; src = t;
      int lo = 0, hi = 2*KLV;
      while (lo < hi) { int mid = (lo+hi)>>1; if (ms[mid] >= v) lo = mid+1; else hi = mid; }
      pos = j + lo;
    }
    fs[pos] = v; p9[pos] = src;
  }
  __syncthreads();

  if (t < NPROP) {
    int src = p9[t];
    float4 f = g_box[b*NPROP + src];
    sb[t] = f;
    sa[t] = (f.z - f.x) * (f.w - f.y);
    g_sbox[b*NPROP + t]   = f;
    g_sscore[b*NPROP + t] = fs[t];
    g_ssrc[b*NPROP + t]   = g_src[b*NPROP + src];
    if (fs[t] > 0.f && (t == NPROP-1 || fs[t+1] <= 0.f)) s_nv = t + 1;
  }
  __syncthreads();

  // suppression bitmatrix in smem: bit(i,j) = IoU>thr & j>i
  for (int x = t; x < NPROP*NWORDS; x += 1024) {
    int i = x / NWORDS;
    int w = x - i*NWORDS;
    float4 bi = sb[i];
    float  ai = sa[i];
    u64 bits = 0;
    int j0   = w * 64;
    int jend = j0 + 64; if (jend > NPROP) jend = NPROP;
    for (int j = (j0 > i+1 ? j0 : i+1); j < jend; j++) {
      float4 bj = sb[j];
      float xx1 = fmaxf(bi.x, bj.x);
      float yy1 = fmaxf(bi.y, bj.y);
      float xx2 = fminf(bi.z, bj.z);
      float yy2 = fminf(bi.w, bj.w);
      float inter = fmaxf(xx2 - xx1, 0.f) * fmaxf(yy2 - yy1, 0.f);
      float iou = inter / (ai + sa[j] - inter + 1e-9f);
      if (iou > NMS_THR) bits |= (1ULL << (j - j0));
    }
    ssup[(size_t)i*NWORDS + w] = bits;
  }
  __syncthreads();

  // greedy walk, warp 0: word-ordered. Invariant: rem[w] is FINAL when word w
  // starts (suppression only points forward). Lane l owns removed-word l in a
  // register. Critical path per kept item: broadcast LDS of the active word's
  // suppressor bits (~29 cyc) + ffs + mask. No ballot/shfl on the hot path.
  if (t < 32) {
    const int lane = t;
    const int nv   = s_nv;
    const int nvw  = nv >> 6, nvb = nv & 63;
    u64 valid = (lane < nvw) ? ~0ULL
              : (lane == nvw ? (nvb ? ((1ULL << nvb) - 1ULL) : 0ULL) : 0ULL);
    u64 rem = ~valid;            // lane's removed-word (lanes >= 15 irrelevant)
    int nk = 0;

    for (int w = 0; w < NWORDS && nk < MAXP; w++) {
      u64 cur = ~__shfl_sync(0xffffffffu, rem, w);   // final avail mask, word w
      while (cur != 0 && nk < MAXP) {
        int bit = __ffsll((long long)cur) - 1;
        int i = (w << 6) + bit;
        if (lane == 0) g_kept[b*MAXP + nk] = i;
        nk++;
        // all lanes: broadcast-load word w of row i (same address, N=1)
        u64 sw = ssup[i*NWORDS + w];
        // lanes < NWORDS: accumulate their own word (conflict-free, off path)
        if (lane < NWORDS) rem |= ssup[i*NWORDS + lane];
        cur &= ~((2ULL << bit) - 1ULL) & ~sw;
      }
    }
    if (lane == 0) g_nkept[b] = nk;
  }
}

// ------- 3) output: box+score + gathered, L2-normalized embedding -------
__global__ void write_kernel(float* __restrict__ out,
                             const float* __restrict__ e0,
                             const float* __restrict__ e1,
                             const float* __restrict__ e2)
{
  const int b = blockIdx.y;
  const int r = blockIdx.x;
  const int tid = threadIdx.x;
  float* o = out + ((size_t)b*MAXP + r)*DPROP;

  if (r >= g_nkept[b]) {                 // zero row (output is poisoned)
    if (tid < DPROP) o[tid] = 0.0f;
    return;
  }

  const int i   = g_kept[b*MAXP + r];
  const int src = g_ssrc[b*NPROP + i];
  const int level = src >> 26;
  const int idx   = src & ((1 << 26) - 1);
  const int H  = (level == 0) ? 76 : (level == 1 ? 38 : 19);
  const int hw = H*H;
  const int r2 = idx % hw;
  const int h  = r2 / H;
  const int w  = r2 - h*H;
  const float* eb = (level == 0 ? e0 : (level == 1 ? e1 : e2));
  const float* e  = eb + (((size_t)b*H + h)*H + w)*EMB;

  float v = (tid < EMB) ? e[tid] : 0.f;

  // warp-shuffle reduction of v*v, then cross-warp via smem
  float p = v*v;
  #pragma unroll
  for (int s = 16; s > 0; s >>= 1) p += __shfl_xor_sync(0xffffffffu, p, s);
  __shared__ float red[8];
  if ((tid & 31) == 0) red[tid >> 5] = p;
  __syncthreads();
  float tot = red[0]+red[1]+red[2]+red[3]+red[4]+red[5]+red[6]+red[7];
  float rinv = rsqrtf(fmaxf(tot, 1e-12f));

  if (tid < EMB) o[5 + tid] = v * rinv;
  if (tid == 0) {
    float4 bx = g_sbox[b*NPROP + i];
    o[0] = bx.x; o[1] = bx.y; o[2] = bx.z; o[3] = bx.w;
    o[4] = g_sscore[b*NPROP + i];
  }
}

// ---------------------------------------------------------------------------
extern "C" void kernel_launch(void* const* d_in, const int* in_sizes, int n_in,
                              void* d_out, int out_size)
{
  const float *p0=nullptr,*p1=nullptr,*p2=nullptr,*e0=nullptr,*e1=nullptr,*e2=nullptr;
  for (int i = 0; i < n_in; i++) {
    switch (in_sizes[i]) {
      case 2217984:  p0 = (const float*)d_in[i]; break;  // pred0 [16,4,76,76,6]
      case 554496:   p1 = (const float*)d_in[i]; break;  // pred1 [16,4,38,38,6]
      case 138624:   p2 = (const float*)d_in[i]; break;  // pred2 [16,4,19,19,6]
      case 19222528: e0 = (const float*)d_in[i]; break;  // emb0 [16,76,76,208]
      case 4805632:  e1 = (const float*)d_in[i]; break;  // emb1 [16,38,38,208]
      case 1201408:  e2 = (const float*)d_in[i]; break;  // emb2 [16,19,19,208]
    }
  }

  cudaFuncSetAttribute(select_kernel, cudaFuncAttributeMaxDynamicSharedMemorySize,
                       NMAX*(int)sizeof(float));
  select_kernel<<<dim3(NB,3), 1024, NMAX*sizeof(float)>>>(p0, p1, p2);

  cudaFuncSetAttribute(nms_kernel, cudaFuncAttributeMaxDynamicSharedMemorySize,
                       NPROP*NWORDS*(int)sizeof(u64));
  nms_kernel<<<NB, 1024, NPROP*NWORDS*sizeof(u64)>>>();

  write_kernel<<<dim3(MAXP, NB), 256>>>((float*)d_out, e0, e1, e2);
}

// round 5
// speedup vs baseline: 2.5652x; 2.3733x over previous
#include <cuda_runtime.h>
#include <cstdint>

typedef unsigned long long u64;

#define NB      16
#define EMB     208
#define KLV     300
#define NPROP   900
#define MAXP    500
#define DPROP   213
#define NWORDS  15      // ceil(900/64)
#define NMS_THR 0.45f
#define NBIN    2048
#define NMAX    23104   // 4*76*76

__constant__ float2 c_anch[3][4] = {
  {{8.f,24.f},{11.f,34.f},{16.f,48.f},{23.f,68.f}},
  {{32.f,96.f},{45.f,135.f},{64.f,192.f},{90.f,271.f}},
  {{128.f,384.f},{180.f,540.f},{256.f,640.f},{512.f,640.f}}
};
__constant__ int   c_H[3]      = {76, 38, 19};
__constant__ float c_stride[3] = {8.f, 16.f, 32.f};

// ---------------- device scratch (no allocations allowed) ----------------
__device__ float4 g_box[NB*NPROP];
__device__ float  g_score[NB*NPROP];
__device__ int    g_src[NB*NPROP];
__device__ float4 g_sbox[NB*NPROP];
__device__ float  g_sscore[NB*NPROP];
__device__ int    g_ssrc[NB*NPROP];
__device__ int    g_nvalid[NB];
__device__ u64    g_supp[NB*NPROP*NWORDS];
__device__ int    g_kept[NB*MAXP];
__device__ int    g_nkept[NB];

// ---------------- 1) fused per-(image,level) select + top-300 ----------------
__global__ void select_kernel(const float* __restrict__ p0,
                              const float* __restrict__ p1,
                              const float* __restrict__ p2)
{
  const int b     = blockIdx.x;
  const int level = blockIdx.y;
  const int tid   = threadIdx.x;
  const int BS    = blockDim.x;           // 1024

  const float* pred = (level == 0) ? p0 : (level == 1) ? p1 : p2;
  const int H = c_H[level], W = H;
  const int N = 4*H*W;
  const float stride = c_stride[level];
  const float scale  = stride / 608.0f;

  extern __shared__ float ds[];           // [N] d-values, N <= 23104
  __shared__ unsigned int hist[NBIN];
  __shared__ unsigned int csum[64];
  __shared__ float cs[NBIN];
  __shared__ int   ci[NBIN];
  __shared__ int   s_cnt, s_tbin;

  for (int i = tid; i < NBIN; i += BS) hist[i] = 0u;
  if (tid == 0) s_cnt = 0;
  __syncthreads();

  const float* pb = pred + (size_t)b * N * 6;

  // pass 1: d = c - a (ALU only), histogram of positives
  for (int i = tid; i < N; i += BS) {
    float2 v = *(const float2*)(pb + (size_t)i*6 + 4);
    float d = v.y - v.x;
    ds[i] = d;
    if (d > 0.0f) {
      int bin = (int)(d * 128.0f);
      bin = bin > NBIN-1 ? NBIN-1 : bin;
      atomicAdd(&hist[bin], 1u);
    }
  }
  __syncthreads();

  if (tid < 64) {
    unsigned s = 0;
    #pragma unroll
    for (int k = 0; k < 32; k++) s += hist[tid*32 + k];
    csum[tid] = s;
  }
  __syncthreads();
  if (tid == 0) {
    unsigned acc = 0;
    int t = 0;
    int c = 63;
    for (; c >= 0; c--) {
      if (acc + csum[c] >= (unsigned)KLV) break;
      acc += csum[c];
    }
    if (c >= 0) {
      int bb = c*32 + 31;
      for (; bb > c*32; bb--) {
        if (acc + hist[bb] >= (unsigned)KLV) break;
        acc += hist[bb];
      }
      t = bb;
    }
    s_tbin = t;
  }
  __syncthreads();
  const int t = s_tbin;

  // pass 2: collect candidates in bins >= t (from smem)
  for (int i = tid; i < N; i += BS) {
    float d = ds[i];
    if (d > 0.0f) {
      int bin = (int)(d * 128.0f);
      bin = bin > NBIN-1 ? NBIN-1 : bin;
      if (bin >= t) {
        int p = atomicAdd(&s_cnt, 1);
        if (p < NBIN) { cs[p] = d; ci[p] = i; }
      }
    }
  }
  __syncthreads();
  int m = s_cnt; if (m > NBIN) m = NBIN;

  // exact conf (matches reference softmax bitwise) for candidates only
  for (int p = tid; p < m; p += BS) {
    float conf = 1.0f / (1.0f + expf(-cs[p]));
    cs[p] = (conf > 0.5f) ? conf : -1.0f;
  }
  int P = 512; while (P < m) P <<= 1;
  for (int i = tid; i < P; i += BS)
    if (i >= m) { cs[i] = -1.0f; ci[i] = 0x7fffffff; }
  __syncthreads();

  // bitonic sort (conf desc, idx asc) over P elements
  for (int k = 2; k <= P; k <<= 1) {
    for (int j = k >> 1; j > 0; j >>= 1) {
      for (int x = tid; x < P; x += BS) {
        int ixj = x ^ j;
        if (ixj > x) {
          float ca = cs[x], cb = cs[ixj];
          int   ia = ci[x], ib = ci[ixj];
          bool later = (ca < cb) || (ca == cb && ia > ib);
          if (later == ((x & k) == 0)) {
            cs[x] = cb; cs[ixj] = ca;
            ci[x] = ib; ci[ixj] = ia;
          }
        }
      }
      __syncthreads();
    }
  }

  // decode + write top-300 (zero-pad shortfall / sub-threshold)
  if (tid < KLV) {
    const int o = b*NPROP + level*KLV + tid;
    if (tid < m && cs[tid] > 0.5f) {
      float conf = cs[tid];
      int   idx  = ci[tid];
      int hw = H*W;
      int a  = idx / hw;
      int r2 = idx - a*hw;
      int h  = r2 / W;
      int w  = r2 - h*W;
      const float* pp = pb + (size_t)idx*6;
      float aw = c_anch[level][a].x / stride;
      float ah = c_anch[level][a].y / stride;
      float x  = pp[0]*aw + (float)w;
      float y  = pp[1]*ah + (float)h;
      float bw = expf(pp[2])*aw;
      float bh = expf(pp[3])*ah;
      float x1 = fminf(fmaxf((x - 0.5f*bw)*scale, 0.0f), 1.0f);
      float y1 = fminf(fmaxf((y - 0.5f*bh)*scale, 0.0f), 1.0f);
      float x2 = fminf(fmaxf((x + 0.5f*bw)*scale, 0.0f), 1.0f);
      float y2 = fminf(fmaxf((y + 0.5f*bh)*scale, 0.0f), 1.0f);
      g_box[o]   = make_float4(x1, y1, x2, y2);
      g_score[o] = conf;
      g_src[o]   = (level << 26) | idx;
    } else {
      g_box[o]   = make_float4(0.f, 0.f, 0.f, 0.f);
      g_score[o] = 0.f;
      g_src[o]   = -1;
    }
  }
}

// ---------------- 2) stable 3-way merge of sorted level lists ----------------
__global__ void merge_kernel()
{
  const int b = blockIdx.x;
  const int t = threadIdx.x;   // 1024
  __shared__ float s[NPROP];
  __shared__ float ms[2*KLV];
  __shared__ int   p6[2*KLV];
  __shared__ float fs[NPROP];
  __shared__ int   p9[NPROP];
  __shared__ int   s_nv;

  if (t < NPROP) s[t] = g_score[b*NPROP + t];
  if (t == 0) s_nv = 0;
  __syncthreads();

  // stage 1: merge [0,300) (A) with [300,600) (B); A wins ties
  if (t < 2*KLV) {
    float v; int pos;
    if (t < KLV) {
      v = s[t];
      int lo = 0, hi = KLV;
      while (lo < hi) { int mid = (lo+hi)>>1; if (s[KLV+mid] > v) lo = mid+1; else hi = mid; }
      pos = t + lo;
    } else {
      int j = t - KLV; v = s[t];
      int lo = 0, hi = KLV;
      while (lo < hi) { int mid = (lo+hi)>>1; if (s[mid] >= v) lo = mid+1; else hi = mid; }
      pos = j + lo;
    }
    ms[pos] = v; p6[pos] = t;
  }
  __syncthreads();

  // stage 2: merge AB (600) with C = [600,900); AB wins ties
  if (t < NPROP) {
    float v; int src, pos;
    if (t < 2*KLV) {
      v = ms[t]; src = p6[t];
      int lo = 0, hi = KLV;
      while (lo < hi) { int mid = (lo+hi)>>1; if (s[2*KLV+mid] > v) lo = mid+1; else hi = mid; }
      pos = t + lo;
    } else {
      int j = t - 2*KLV; v = s[t]; src = t;
      int lo = 0, hi = 2*KLV;
      while (lo < hi) { int mid = (lo+hi)>>1; if (ms[mid] >= v) lo = mid+1; else hi = mid; }
      pos = j + lo;
    }
    fs[pos] = v; p9[pos] = src;
  }
  __syncthreads();

  if (t < NPROP) {
    int src = p9[t];
    g_sbox[b*NPROP + t]   = g_box[b*NPROP + src];
    g_sscore[b*NPROP + t] = fs[t];
    g_ssrc[b*NPROP + t]   = g_src[b*NPROP + src];
    if (fs[t] > 0.f && (t == NPROP-1 || fs[t+1] <= 0.f)) s_nv = t + 1;
  }
  __syncthreads();
  if (t == 0) g_nvalid[b] = s_nv;
}

// ------- 3) suppression bitmatrix, CHIP-WIDE (240 blocks): bit(i,j)=IoU>thr & j>i -------
// SoA smem staging: per-lane random j access hits 4B banks (1-2 cyc) instead of
// float4 16B phases.
__global__ void supp_kernel()
{
  const int b  = blockIdx.y;
  const int i0 = blockIdx.x * 64;
  __shared__ float sx1[NPROP], sy1[NPROP], sx2[NPROP], sy2[NPROP], sa[NPROP];
  for (int i = threadIdx.x; i < NPROP; i += blockDim.x) {
    float4 f = g_sbox[b*NPROP + i];
    sx1[i] = f.x; sy1[i] = f.y; sx2[i] = f.z; sy2[i] = f.w;
    sa[i]  = (f.z - f.x) * (f.w - f.y);
  }
  __syncthreads();

  int i = i0 + threadIdx.x / NWORDS;
  int w = threadIdx.x % NWORDS;
  if (i < NPROP) {
    float bx1 = sx1[i], by1 = sy1[i], bx2 = sx2[i], by2 = sy2[i], ai = sa[i];
    u64 bits = 0;
    int j0   = w * 64;
    int jend = j0 + 64; if (jend > NPROP) jend = NPROP;
    for (int j = (j0 > i+1 ? j0 : i+1); j < jend; j++) {
      float xx1 = fmaxf(bx1, sx1[j]);
      float yy1 = fmaxf(by1, sy1[j]);
      float xx2 = fminf(bx2, sx2[j]);
      float yy2 = fminf(by2, sy2[j]);
      float inter = fmaxf(xx2 - xx1, 0.f) * fmaxf(yy2 - yy1, 0.f);
      float iou = inter / (ai + sa[j] - inter + 1e-9f);
      if (iou > NMS_THR) bits |= (1ULL << (j - j0));
    }
    g_supp[((size_t)b*NPROP + i)*NWORDS + w] = bits;
  }
}

// ------- 4) greedy walk per image: warp 0, word-ordered register bitmask -------
// Invariant: rem[w] is FINAL when word w starts (suppression points forward).
// Lane l owns removed-word l in a register. Per kept item: one broadcast LDS
// (active word's suppressor bits) + ffs + mask. No ballot/shfl on hot path.
__global__ void greedy_kernel()
{
  const int b = blockIdx.x;
  extern __shared__ u64 ssup[];   // 900*15 u64 = 108000 B
  for (int x = threadIdx.x; x < NPROP*NWORDS; x += blockDim.x)
    ssup[x] = g_supp[(size_t)b*NPROP*NWORDS + x];
  __syncthreads();
  if (threadIdx.x >= 32) return;

  const int lane = threadIdx.x;
  const int nv   = g_nvalid[b];
  const int nvw  = nv >> 6, nvb = nv & 63;
  u64 valid = (lane < nvw) ? ~0ULL
            : (lane == nvw ? (nvb ? ((1ULL << nvb) - 1ULL) : 0ULL) : 0ULL);
  u64 rem = ~valid;
  int nk = 0;

  for (int w = 0; w < NWORDS && nk < MAXP; w++) {
    u64 cur = ~__shfl_sync(0xffffffffu, rem, w);   // final avail mask, word w
    while (cur != 0 && nk < MAXP) {
      int bit = __ffsll((long long)cur) - 1;
      int i = (w << 6) + bit;
      if (lane == 0) g_kept[b*MAXP + nk] = i;
      nk++;
      u64 sw = ssup[i*NWORDS + w];                 // broadcast (N=1)
      if (lane < NWORDS) rem |= ssup[i*NWORDS + lane];  // off critical path
      cur &= ~((2ULL << bit) - 1ULL) & ~sw;
    }
  }
  if (lane == 0) g_nkept[b] = nk;
}

// ------- 5) output: box+score + gathered, L2-normalized embedding -------
__global__ void write_kernel(float* __restrict__ out,
                             const float* __restrict__ e0,
                             const float* __restrict__ e1,
                             const float* __restrict__ e2)
{
  const int b = blockIdx.y;
  const int r = blockIdx.x;
  const int tid = threadIdx.x;
  float* o = out + ((size_t)b*MAXP + r)*DPROP;

  if (r >= g_nkept[b]) {                 // zero row (output is poisoned)
    if (tid < DPROP) o[tid] = 0.0f;
    return;
  }

  const int i   = g_kept[b*MAXP + r];
  const int src = g_ssrc[b*NPROP + i];
  const int level = src >> 26;
  const int idx   = src & ((1 << 26) - 1);
  const int H  = (level == 0) ? 76 : (level == 1 ? 38 : 19);
  const int hw = H*H;
  const int r2 = idx % hw;
  const int h  = r2 / H;
  const int w  = r2 - h*H;
  const float* eb = (level == 0 ? e0 : (level == 1 ? e1 : e2));
  const float* e  = eb + (((size_t)b*H + h)*H + w)*EMB;

  float v = (tid < EMB) ? e[tid] : 0.f;

  float p = v*v;
  #pragma unroll
  for (int s = 16; s > 0; s >>= 1) p += __shfl_xor_sync(0xffffffffu, p, s);
  __shared__ float red[8];
  if ((tid & 31) == 0) red[tid >> 5] = p;
  __syncthreads();
  float tot = red[0]+red[1]+red[2]+red[3]+red[4]+red[5]+red[6]+red[7];
  float rinv = rsqrtf(fmaxf(tot, 1e-12f));

  if (tid < EMB) o[5 + tid] = v * rinv;
  if (tid == 0) {
    float4 bx = g_sbox[b*NPROP + i];
    o[0] = bx.x; o[1] = bx.y; o[2] = bx.z; o[3] = bx.w;
    o[4] = g_sscore[b*NPROP + i];
  }
}

// ---------------------------------------------------------------------------
extern "C" void kernel_launch(void* const* d_in, const int* in_sizes, int n_in,
                              void* d_out, int out_size)
{
  const float *p0=nullptr,*p1=nullptr,*p2=nullptr,*e0=nullptr,*e1=nullptr,*e2=nullptr;
  for (int i = 0; i < n_in; i++) {
    switch (in_sizes[i]) {
      case 2217984:  p0 = (const float*)d_in[i]; break;  // pred0 [16,4,76,76,6]
      case 554496:   p1 = (const float*)d_in[i]; break;  // pred1 [16,4,38,38,6]
      case 138624:   p2 = (const float*)d_in[i]; break;  // pred2 [16,4,19,19,6]
      case 19222528: e0 = (const float*)d_in[i]; break;  // emb0 [16,76,76,208]
      case 4805632:  e1 = (const float*)d_in[i]; break;  // emb1 [16,38,38,208]
      case 1201408:  e2 = (const float*)d_in[i]; break;  // emb2 [16,19,19,208]
    }
  }

  cudaFuncSetAttribute(select_kernel, cudaFuncAttributeMaxDynamicSharedMemorySize,
                       NMAX*(int)sizeof(float));
  select_kernel<<<dim3(NB,3), 1024, NMAX*sizeof(float)>>>(p0, p1, p2);

  merge_kernel<<<NB, 1024>>>();
  supp_kernel<<<dim3(15, NB), 960>>>();

  cudaFuncSetAttribute(greedy_kernel, cudaFuncAttributeMaxDynamicSharedMemorySize,
                       NPROP*NWORDS*(int)sizeof(u64));
  greedy_kernel<<<NB, 1024, NPROP*NWORDS*sizeof(u64)>>>();

  write_kernel<<<dim3(MAXP, NB), 256>>>((float*)d_out, e0, e1, e2);
}